// round 3
// baseline (speedup 1.0000x reference)
#include <cuda_runtime.h>
#include <math.h>

#define FEAT  52
#define NPIX  2704
#define NA    24336
#define NSORT 32768
#define PRE   12000
#define POST  2000
#define NCB   188

#define OUT_ROIS 0
#define OUT_LOCS 8000
#define OUT_CLS1 105344
#define OUT_OBJ  154016
#define OUT_CLS2 178352

#define SMEM_CONV ((256*3*54 + 128*64) * 4)

// ---------------- device scratch (static, no allocs) ----------------
__device__ float  g_wt[2304 * 256];           // [(kh*3+kw)*256+ci][co]
__device__ float4 g_h4[NPIX * 64];            // conv1 output, [p][256]
__device__ float4 g_roi4[NA];
__device__ unsigned char g_valid[NA];
__device__ unsigned long long g_key[NSORT];
__device__ float4 g_sbox[PRE];
__device__ float  g_sarea[PRE];
__device__ unsigned long long g_mask[(size_t)PRE * NCB];
__device__ unsigned long long g_rem0[NCB];

// ---------------- Cephes/Eigen-style expf (matches XLA CPU vectorized exp) --
__device__ __forceinline__ float cephes_expf(float x) {
    float m = floorf(fmaf(x, 1.44269504088896341f, 0.5f));
    float r = fmaf(m, -0.693359375f, x);
    r = fmaf(m, 2.12194440e-4f, r);
    float r2 = __fmul_rn(r, r);
    float y = 1.9875691500E-4f;
    y = fmaf(y, r, 1.3981999507E-3f);
    y = fmaf(y, r, 8.3334519073E-3f);
    y = fmaf(y, r, 4.1665795894E-2f);
    y = fmaf(y, r, 1.6666665459E-1f);
    y = fmaf(y, r, 5.0000001201E-1f);
    y = fmaf(y, r2, r);
    y = __fadd_rn(y, 1.0f);
    return ldexpf(y, (int)m);
}

// ---------------- 1: weight transpose to [(kh*3+kw)*256+ci][co] -----------
__global__ void k_wt(const float* __restrict__ w) {
    int o = blockIdx.x * 256 + threadIdx.x;
    if (o < 2304 * 256) {
        int co  = o & 255;
        int k   = o >> 8;            // k = khw*256 + ci
        int ci  = k & 255;
        int khw = k >> 8;            // kh*3+kw
        g_wt[o] = w[co * 2304 + ci * 9 + khw];
    }
}

// ---------------- 2: conv1 3x3 SAME 256->256, strict (kh,kw,ci) FMA chain --
// grid (4 cog, 52 y), 208 threads: quad = t&15 (4 co), pxg = t>>4 (4 px)
__global__ __launch_bounds__(208) void k_conv(const float* __restrict__ x,
                                              const float* __restrict__ bias) {
    extern __shared__ float smem[];
    float* s_in = smem;                       // [ci*3+row][54]  (col = xx+1)
    float* s_w  = smem + 256 * 3 * 54;        // [ci_local][64co]
    int t = threadIdx.x;
    int cog = blockIdx.x, y = blockIdx.y;
    int quad = t & 15;
    int pxg  = t >> 4;

    float acc[4][4];
#pragma unroll
    for (int c = 0; c < 4; c++)
#pragma unroll
        for (int j = 0; j < 4; j++) acc[c][j] = 0.f;

    // stage full input tile: 256 ci x 3 rows x 54 cols (zero-padded halo)
    for (int e = t; e < 256 * 3 * 54; e += 208) {
        int ci  = e / 162;
        int rem = e - ci * 162;
        int row = rem / 54;
        int col = rem - row * 54;
        int yy = y + row - 1;
        int xx = col - 1;
        float v = 0.f;
        if ((unsigned)yy < 52u && (unsigned)xx < 52u)
            v = x[ci * NPIX + yy * 52 + xx];
        s_in[e] = v;
    }

    for (int khw = 0; khw < 9; khw++) {
        int kh = khw / 3, kw = khw - 3 * (khw / 3);
        for (int half = 0; half < 2; half++) {
            __syncthreads();
            for (int e = t; e < 8192; e += 208)
                s_w[e] = g_wt[((khw << 8) + (half << 7) + (e >> 6)) * 256 + cog * 64 + (e & 63)];
            __syncthreads();
            int inbase = (half * 128) * 162 + kh * 54 + pxg * 4 + kw;
#pragma unroll 4
            for (int ci = 0; ci < 128; ci++) {
                const float* ip = &s_in[inbase + ci * 162];
                float v0 = ip[0], v1 = ip[1], v2 = ip[2], v3 = ip[3];
                const float4 wv = *(const float4*)&s_w[ci * 64 + quad * 4];
                acc[0][0] = fmaf(wv.x, v0, acc[0][0]);
                acc[0][1] = fmaf(wv.x, v1, acc[0][1]);
                acc[0][2] = fmaf(wv.x, v2, acc[0][2]);
                acc[0][3] = fmaf(wv.x, v3, acc[0][3]);
                acc[1][0] = fmaf(wv.y, v0, acc[1][0]);
                acc[1][1] = fmaf(wv.y, v1, acc[1][1]);
                acc[1][2] = fmaf(wv.y, v2, acc[1][2]);
                acc[1][3] = fmaf(wv.y, v3, acc[1][3]);
                acc[2][0] = fmaf(wv.z, v0, acc[2][0]);
                acc[2][1] = fmaf(wv.z, v1, acc[2][1]);
                acc[2][2] = fmaf(wv.z, v2, acc[2][2]);
                acc[2][3] = fmaf(wv.z, v3, acc[2][3]);
                acc[3][0] = fmaf(wv.w, v0, acc[3][0]);
                acc[3][1] = fmaf(wv.w, v1, acc[3][1]);
                acc[3][2] = fmaf(wv.w, v2, acc[3][2]);
                acc[3][3] = fmaf(wv.w, v3, acc[3][3]);
            }
        }
    }

    float* h = (float*)g_h4;
#pragma unroll
    for (int c = 0; c < 4; c++) {
        int co = cog * 64 + quad * 4 + c;
        float b = bias[co];
#pragma unroll
        for (int j = 0; j < 4; j++) {
            int px = pxg * 4 + j;
            h[(y * 52 + px) * 256 + co] = __fadd_rn(acc[c][j], b);
        }
    }
}

// ---------------- 3a: reg head (1x1, 256->36), ci-ascending FMA chain -----
__global__ __launch_bounds__(64) void k_head_reg(const float* __restrict__ rw,
                                                 const float* __restrict__ rb,
                                                 float* __restrict__ out) {
    __shared__ float4 s_w[36 * 64];
    int t = threadIdx.x;
    const float4* rw4 = (const float4*)rw;
    for (int e = t; e < 36 * 64; e += 64) s_w[e] = rw4[e];
    __syncthreads();
    int p = blockIdx.x * 64 + t;
    if (p >= NPIX) return;
    float acc[36];
#pragma unroll
    for (int o = 0; o < 36; o++) acc[o] = 0.f;
    const float4* hp = g_h4 + (size_t)p * 64;
    for (int c4 = 0; c4 < 64; c4++) {
        float4 v = hp[c4];
#pragma unroll
        for (int o = 0; o < 36; o++) {
            float4 w = s_w[o * 64 + c4];
            acc[o] = fmaf(w.x, v.x, acc[o]);
            acc[o] = fmaf(w.y, v.y, acc[o]);
            acc[o] = fmaf(w.z, v.z, acc[o]);
            acc[o] = fmaf(w.w, v.w, acc[o]);
        }
    }
    int base = p * 9;
#pragma unroll
    for (int a = 0; a < 9; a++)
#pragma unroll
        for (int c = 0; c < 4; c++)
            out[OUT_LOCS + (base + a) * 4 + c] = __fadd_rn(acc[a * 4 + c], __ldg(rb + a * 4 + c));
}

// ---------------- 3b: cls head (1x1, 256->18) ------------------------------
__global__ __launch_bounds__(64) void k_head_cls(const float* __restrict__ cw,
                                                 const float* __restrict__ cb,
                                                 float* __restrict__ out) {
    __shared__ float4 s_w[18 * 64];
    int t = threadIdx.x;
    const float4* cw4 = (const float4*)cw;
    for (int e = t; e < 18 * 64; e += 64) s_w[e] = cw4[e];
    __syncthreads();
    int p = blockIdx.x * 64 + t;
    if (p >= NPIX) return;
    float acc[18];
#pragma unroll
    for (int o = 0; o < 18; o++) acc[o] = 0.f;
    const float4* hp = g_h4 + (size_t)p * 64;
    for (int c4 = 0; c4 < 64; c4++) {
        float4 v = hp[c4];
#pragma unroll
        for (int o = 0; o < 18; o++) {
            float4 w = s_w[o * 64 + c4];
            acc[o] = fmaf(w.x, v.x, acc[o]);
            acc[o] = fmaf(w.y, v.y, acc[o]);
            acc[o] = fmaf(w.z, v.z, acc[o]);
            acc[o] = fmaf(w.w, v.w, acc[o]);
        }
    }
    int base = p * 9;
#pragma unroll
    for (int a = 0; a < 9; a++) {
#pragma unroll
        for (int c = 0; c < 2; c++) {
            float v = __fadd_rn(acc[a * 2 + c], __ldg(cb + a * 2 + c));
            out[OUT_CLS1 + (base + a) * 2 + c] = v;
            out[OUT_CLS2 + (base + a) * 2 + c] = v;
            if (c == 1) out[OUT_OBJ + base + a] = v;
        }
    }
}

// ---------------- 4: anchor decode + sort keys (no FMA contraction) -------
__global__ void k_decode(float* __restrict__ out) {
    int i = blockIdx.x * 256 + threadIdx.x;
    if (i < NCB)  g_rem0[i] = 0ull;
    if (i < 8000) out[OUT_ROIS + i] = 0.f;
    if (i >= NSORT) return;
    if (i >= NA) { g_key[i] = ~0ull; return; }

    int p = i / 9, a = i - p * 9;
    int ri = a / 3, si = a - ri * 3;
    double ratio = (ri == 0) ? 0.5 : (ri == 1 ? 1.0 : 2.0);
    double scale = (si == 0) ? 4.0 : (si == 1 ? 8.0 : 16.0);
    double hd = 4.0 * scale * sqrt(ratio);
    double wd = 4.0 * scale * sqrt(1.0 / ratio);
    double cyd = (double)(4 * (p / 52) + 2);
    double cxd = (double)(4 * (p % 52) + 2);
    float a0 = (float)(cyd - hd * 0.5);
    float a1 = (float)(cxd - wd * 0.5);
    float a2 = (float)(cyd + hd * 0.5);
    float a3 = (float)(cxd + wd * 0.5);

    float ah = __fsub_rn(a2, a0), aw = __fsub_rn(a3, a1);
    float acy = __fadd_rn(a0, __fmul_rn(0.5f, ah));
    float acx = __fadd_rn(a1, __fmul_rn(0.5f, aw));

    float l0 = out[OUT_LOCS + i * 4 + 0];
    float l1 = out[OUT_LOCS + i * 4 + 1];
    float l2 = out[OUT_LOCS + i * 4 + 2];
    float l3 = out[OUT_LOCS + i * 4 + 3];
    float s  = out[OUT_OBJ + i];

    float cy = __fadd_rn(__fmul_rn(l0, ah), acy);
    float cx = __fadd_rn(__fmul_rn(l1, aw), acx);
    float hh = __fmul_rn(cephes_expf(l2), ah);
    float ww = __fmul_rn(cephes_expf(l3), aw);
    float r0 = __fsub_rn(cy, __fmul_rn(0.5f, hh));
    float r1 = __fsub_rn(cx, __fmul_rn(0.5f, ww));
    float r2 = __fadd_rn(cy, __fmul_rn(0.5f, hh));
    float r3 = __fadd_rn(cx, __fmul_rn(0.5f, ww));
    r0 = fminf(fmaxf(r0, 0.f), 210.f);
    r1 = fminf(fmaxf(r1, 0.f), 210.f);
    r2 = fminf(fmaxf(r2, 0.f), 210.f);
    r3 = fminf(fmaxf(r3, 0.f), 210.f);
    float hs = __fsub_rn(r2, r0), ws = __fsub_rn(r3, r1);
    bool valid = (hs >= 16.f) && (ws >= 16.f);

    g_roi4[i] = make_float4(r0, r1, r2, r3);
    g_valid[i] = valid ? 1 : 0;

    float sm = valid ? s : __int_as_float(0xff800000);
    unsigned u = __float_as_uint(sm);
    u = (u & 0x80000000u) ? ~u : (u | 0x80000000u);
    g_key[i] = ((unsigned long long)(~u) << 32) | (unsigned long long)(unsigned)i;
}

// ---------------- 5: bitonic sort (32768 keys ascending) -------------------
__device__ __forceinline__ void cswap(unsigned long long& a, unsigned long long& b, bool asc) {
    bool sw = asc ? (a > b) : (a < b);
    if (sw) { unsigned long long tt = a; a = b; b = tt; }
}

__device__ void bitonic_tile(unsigned long long* sk, int base, int t, int s, int jmax) {
    for (int j = jmax; j >= 1; j >>= 1) {
        __syncthreads();
#pragma unroll
        for (int q = 0; q < 2; q++) {
            int p = t + q * 1024;
            int i = 2 * p - (p & (j - 1));
            bool asc = (((base + i) & s) == 0);
            unsigned long long a = sk[i], b = sk[i + j];
            cswap(a, b, asc);
            sk[i] = a; sk[i + j] = b;
        }
    }
}

__global__ __launch_bounds__(1024) void k_sort_local_full() {
    __shared__ unsigned long long sk[4096];
    int t = threadIdx.x, base = blockIdx.x * 4096;
#pragma unroll
    for (int q = 0; q < 4; q++) sk[t + q * 1024] = g_key[base + t + q * 1024];
    for (int s = 2; s <= 4096; s <<= 1) bitonic_tile(sk, base, t, s, s >> 1);
    __syncthreads();
#pragma unroll
    for (int q = 0; q < 4; q++) g_key[base + t + q * 1024] = sk[t + q * 1024];
}

__global__ __launch_bounds__(1024) void k_sort_local_tail(int s) {
    __shared__ unsigned long long sk[4096];
    int t = threadIdx.x, base = blockIdx.x * 4096;
#pragma unroll
    for (int q = 0; q < 4; q++) sk[t + q * 1024] = g_key[base + t + q * 1024];
    bitonic_tile(sk, base, t, s, 2048);
    __syncthreads();
#pragma unroll
    for (int q = 0; q < 4; q++) g_key[base + t + q * 1024] = sk[t + q * 1024];
}

__global__ void k_sort_global(int j, int s) {
    int p = blockIdx.x * 256 + threadIdx.x;
    int i = 2 * p - (p & (j - 1));
    bool asc = ((i & s) == 0);
    unsigned long long a = g_key[i], b = g_key[i + j];
    cswap(a, b, asc);
    g_key[i] = a; g_key[i + j] = b;
}

// ---------------- 6: gather sorted boxes -----------------------------------
__global__ void k_gather() {
    int i = blockIdx.x * 256 + threadIdx.x;
    if (i >= PRE) return;
    unsigned idx = (unsigned)(g_key[i] & 0xFFFFFFFFull);
    float4 b = g_roi4[idx];
    g_sbox[i] = b;
    g_sarea[i] = __fmul_rn(__fadd_rn(__fsub_rn(b.w, b.y), 1.f),
                           __fadd_rn(__fsub_rn(b.z, b.x), 1.f));
    if (!g_valid[idx]) atomicOr(&g_rem0[i >> 6], 1ull << (i & 63));
}

// ---------------- 7: IoU suppression-mask matrix (upper triangle) ----------
__global__ __launch_bounds__(64) void k_mask() {
    int rc = blockIdx.y, cc = blockIdx.x;
    if (cc < rc) return;
    int t = threadIdx.x;
    __shared__ float4 cb[64];
    __shared__ float  ca[64];
    int jg = cc * 64 + t;
    if (jg < PRE) { cb[t] = g_sbox[jg]; ca[t] = g_sarea[jg]; }
    else          { cb[t] = make_float4(0.f, 0.f, 0.f, 0.f); ca[t] = 0.f; }
    __syncthreads();
    int ig = rc * 64 + t;
    if (ig >= PRE) return;
    float4 b = g_sbox[ig];
    float ai = g_sarea[ig];
    unsigned long long bits = 0ull;
    int jmax = min(64, PRE - cc * 64);
    for (int j = 0; j < jmax; j++) {
        int jj = cc * 64 + j;
        if (jj <= ig) continue;
        float4 c = cb[j];
        float yy1 = fmaxf(b.x, c.x), xx1 = fmaxf(b.y, c.y);
        float yy2 = fminf(b.z, c.z), xx2 = fminf(b.w, c.w);
        float dx = __fadd_rn(__fsub_rn(xx2, xx1), 1.f);
        float dy = __fadd_rn(__fsub_rn(yy2, yy1), 1.f);
        float inter = __fmul_rn(fmaxf(0.f, dx), fmaxf(0.f, dy));
        float denom = __fsub_rn(__fadd_rn(ai, ca[j]), inter);
        float iou = __fdiv_rn(inter, denom);
        if (iou > 0.7f) bits |= (1ull << j);
    }
    g_mask[(size_t)ig * NCB + cc] = bits;
}

// ---------------- 8: chunked greedy NMS + ROI write ------------------------
__global__ __launch_bounds__(256) void k_nms(float* __restrict__ out) {
    __shared__ unsigned long long remv[NCB];
    __shared__ unsigned long long sdiag[64];
    __shared__ unsigned long long s_kept;
    __shared__ int s_base, s_stop;
    int t = threadIdx.x;
    if (t < NCB) remv[t] = g_rem0[t];
    if (t == 0) { s_base = 0; s_stop = 0; }
    __syncthreads();
    for (int c = 0; c < NCB; c++) {
        if (t < 64) {
            int row = c * 64 + t;
            sdiag[t] = (row < PRE) ? g_mask[(size_t)row * NCB + c] : 0ull;
        }
        __syncthreads();
        if (t == 0) {
            unsigned long long sup = remv[c];
            if (c == NCB - 1) sup |= ~((1ull << 32) - 1ull);   // rows >= PRE (12000%64==32)
            unsigned long long kept = 0ull;
            for (int i = 0; i < 64; i++) {
                if (!((sup >> i) & 1ull)) {
                    kept |= (1ull << i);
                    sup |= sdiag[i];
                }
            }
            s_kept = kept;
        }
        __syncthreads();
        unsigned long long kept = s_kept;
        int base = s_base;
        if (t < 64 && ((kept >> t) & 1ull)) {
            int pos = base + __popcll(kept & ((1ull << t) - 1ull));
            if (pos < POST) {
                float4 b = g_sbox[c * 64 + t];
                out[OUT_ROIS + pos * 4 + 0] = b.x;
                out[OUT_ROIS + pos * 4 + 1] = b.y;
                out[OUT_ROIS + pos * 4 + 2] = b.z;
                out[OUT_ROIS + pos * 4 + 3] = b.w;
            }
        }
        unsigned long long acc = 0ull;
        if (t > c && t < NCB) {
            acc = remv[t];
            unsigned long long k2 = kept;
            while (k2) {
                int i = __ffsll((long long)k2) - 1;
                k2 &= (k2 - 1ull);
                acc |= g_mask[(size_t)(c * 64 + i) * NCB + t];
            }
        }
        __syncthreads();
        if (t > c && t < NCB) remv[t] = acc;
        if (t == 0) {
            s_base = base + __popcll(kept);
            s_stop = (s_base >= POST) ? 1 : 0;
        }
        __syncthreads();
        if (s_stop) return;
    }
}

// ---------------- launch ----------------------------------------------------
extern "C" void kernel_launch(void* const* d_in, const int* in_sizes, int n_in,
                              void* d_out, int out_size) {
    const float* x   = (const float*)d_in[0];
    const float* c1w = (const float*)d_in[1];
    const float* c1b = (const float*)d_in[2];
    const float* rw  = (const float*)d_in[3];
    const float* rb  = (const float*)d_in[4];
    const float* cw  = (const float*)d_in[5];
    const float* cb  = (const float*)d_in[6];
    float* out = (float*)d_out;

    cudaFuncSetAttribute(k_conv, cudaFuncAttributeMaxDynamicSharedMemorySize, SMEM_CONV);

    k_wt<<<2304, 256>>>(c1w);
    k_conv<<<dim3(4, 52), 208, SMEM_CONV>>>(x, c1b);
    k_head_reg<<<43, 64>>>(rw, rb, out);
    k_head_cls<<<43, 64>>>(cw, cb, out);
    k_decode<<<128, 256>>>(out);

    k_sort_local_full<<<8, 1024>>>();
    k_sort_global<<<64, 256>>>(4096, 8192);
    k_sort_local_tail<<<8, 1024>>>(8192);
    k_sort_global<<<64, 256>>>(8192, 16384);
    k_sort_global<<<64, 256>>>(4096, 16384);
    k_sort_local_tail<<<8, 1024>>>(16384);
    k_sort_global<<<64, 256>>>(16384, 32768);
    k_sort_global<<<64, 256>>>(8192, 32768);
    k_sort_global<<<64, 256>>>(4096, 32768);
    k_sort_local_tail<<<8, 1024>>>(32768);

    k_gather<<<47, 256>>>();
    k_mask<<<dim3(NCB, NCB), 64>>>();
    k_nms<<<1, 256>>>(out);
}

// round 4
// speedup vs baseline: 1.0478x; 1.0478x over previous
#include <cuda_runtime.h>
#include <math.h>

#define FEAT  52
#define NPIX  2704
#define NA    24336
#define NSORT 32768
#define PRE   12000
#define POST  2000
#define NCB   188

#define OUT_ROIS 0
#define OUT_LOCS 8000
#define OUT_CLS1 105344
#define OUT_OBJ  154016
#define OUT_CLS2 178352

#define SMEM_CONV ((256*3*54 + 128*64) * 4)

// ---------------- device scratch (static, no allocs) ----------------
__device__ float  g_wt[2304 * 256];           // [(kh*3+kw)*256+ci][co]
__device__ float4 g_h4[NPIX * 64];            // conv1 output, [p][256]
__device__ float4 g_roi4[NA];
__device__ unsigned char g_valid[NA];
__device__ unsigned long long g_key[NSORT];
__device__ float4 g_sbox[PRE];
__device__ float  g_sarea[PRE];
__device__ unsigned long long g_mask[(size_t)PRE * NCB];
__device__ unsigned long long g_rem0[NCB];

// ---------------- Cephes/Eigen-style expf (matches XLA CPU vectorized exp) --
__device__ __forceinline__ float cephes_expf(float x) {
    float m = floorf(fmaf(x, 1.44269504088896341f, 0.5f));
    float r = fmaf(m, -0.693359375f, x);
    r = fmaf(m, 2.12194440e-4f, r);
    float r2 = __fmul_rn(r, r);
    float y = 1.9875691500E-4f;
    y = fmaf(y, r, 1.3981999507E-3f);
    y = fmaf(y, r, 8.3334519073E-3f);
    y = fmaf(y, r, 4.1665795894E-2f);
    y = fmaf(y, r, 1.6666665459E-1f);
    y = fmaf(y, r, 5.0000001201E-1f);
    y = fmaf(y, r2, r);
    y = __fadd_rn(y, 1.0f);
    return ldexpf(y, (int)m);
}

// ---------------- 1: weight transpose to [(kh*3+kw)*256+ci][co] -----------
__global__ void k_wt(const float* __restrict__ w) {
    int o = blockIdx.x * 256 + threadIdx.x;
    if (o < 2304 * 256) {
        int co  = o & 255;
        int k   = o >> 8;
        int ci  = k & 255;
        int khw = k >> 8;
        g_wt[o] = w[co * 2304 + ci * 9 + khw];
    }
}

// ---------------- 2: conv1 3x3 SAME 256->256, strict (kh,kw,ci) FMA chain --
__global__ __launch_bounds__(208) void k_conv(const float* __restrict__ x,
                                              const float* __restrict__ bias) {
    extern __shared__ float smem[];
    float* s_in = smem;                       // [ci*3+row][54]
    float* s_w  = smem + 256 * 3 * 54;        // [ci_local][64co]
    int t = threadIdx.x;
    int cog = blockIdx.x, y = blockIdx.y;
    int quad = t & 15;
    int pxg  = t >> 4;

    float acc[4][4];
#pragma unroll
    for (int c = 0; c < 4; c++)
#pragma unroll
        for (int j = 0; j < 4; j++) acc[c][j] = 0.f;

    for (int e = t; e < 256 * 3 * 54; e += 208) {
        int ci  = e / 162;
        int rem = e - ci * 162;
        int row = rem / 54;
        int col = rem - row * 54;
        int yy = y + row - 1;
        int xx = col - 1;
        float v = 0.f;
        if ((unsigned)yy < 52u && (unsigned)xx < 52u)
            v = x[ci * NPIX + yy * 52 + xx];
        s_in[e] = v;
    }

    for (int khw = 0; khw < 9; khw++) {
        int kh = khw / 3, kw = khw - 3 * (khw / 3);
        for (int half = 0; half < 2; half++) {
            __syncthreads();
            for (int e = t; e < 8192; e += 208)
                s_w[e] = g_wt[((khw << 8) + (half << 7) + (e >> 6)) * 256 + cog * 64 + (e & 63)];
            __syncthreads();
            int inbase = (half * 128) * 162 + kh * 54 + pxg * 4 + kw;
#pragma unroll 4
            for (int ci = 0; ci < 128; ci++) {
                const float* ip = &s_in[inbase + ci * 162];
                float v0 = ip[0], v1 = ip[1], v2 = ip[2], v3 = ip[3];
                const float4 wv = *(const float4*)&s_w[ci * 64 + quad * 4];
                acc[0][0] = fmaf(wv.x, v0, acc[0][0]);
                acc[0][1] = fmaf(wv.x, v1, acc[0][1]);
                acc[0][2] = fmaf(wv.x, v2, acc[0][2]);
                acc[0][3] = fmaf(wv.x, v3, acc[0][3]);
                acc[1][0] = fmaf(wv.y, v0, acc[1][0]);
                acc[1][1] = fmaf(wv.y, v1, acc[1][1]);
                acc[1][2] = fmaf(wv.y, v2, acc[1][2]);
                acc[1][3] = fmaf(wv.y, v3, acc[1][3]);
                acc[2][0] = fmaf(wv.z, v0, acc[2][0]);
                acc[2][1] = fmaf(wv.z, v1, acc[2][1]);
                acc[2][2] = fmaf(wv.z, v2, acc[2][2]);
                acc[2][3] = fmaf(wv.z, v3, acc[2][3]);
                acc[3][0] = fmaf(wv.w, v0, acc[3][0]);
                acc[3][1] = fmaf(wv.w, v1, acc[3][1]);
                acc[3][2] = fmaf(wv.w, v2, acc[3][2]);
                acc[3][3] = fmaf(wv.w, v3, acc[3][3]);
            }
        }
    }

    float* h = (float*)g_h4;
#pragma unroll
    for (int c = 0; c < 4; c++) {
        int co = cog * 64 + quad * 4 + c;
        float b = bias[co];
#pragma unroll
        for (int j = 0; j < 4; j++) {
            int px = pxg * 4 + j;
            h[(y * 52 + px) * 256 + co] = __fadd_rn(acc[c][j], b);
        }
    }
}

// ---------------- 3: fused 1x1 heads (256->36 reg, 256->18 cls) ------------
// 216 threads: px = t/54 (4 px per block), o = t%54 (0..35 reg, 36..53 cls)
__global__ __launch_bounds__(216) void k_heads(const float* __restrict__ rw,
                                               const float* __restrict__ rb,
                                               const float* __restrict__ cw,
                                               const float* __restrict__ cbp,
                                               float* __restrict__ out) {
    __shared__ float s_h[4 * 256];
    __shared__ float s_w[54 * 129];
    int t = threadIdx.x;
    int pxb = blockIdx.x * 4;
    const float* h = (const float*)g_h4;
    for (int e = t; e < 1024; e += 216)
        s_h[e] = h[(size_t)pxb * 256 + e];

    int px = t / 54;
    int o  = t - px * 54;
    float acc = 0.f;
    for (int hs = 0; hs < 2; hs++) {
        __syncthreads();
        for (int e = t; e < 54 * 128; e += 216) {
            int oo = e >> 7, ci = e & 127;
            float wv = (oo < 36) ? rw[oo * 256 + hs * 128 + ci]
                                 : cw[(oo - 36) * 256 + hs * 128 + ci];
            s_w[oo * 129 + ci] = wv;
        }
        __syncthreads();
        const float* hp = &s_h[px * 256 + hs * 128];
        const float* wp = &s_w[o * 129];
#pragma unroll 8
        for (int ci = 0; ci < 128; ci++)
            acc = fmaf(wp[ci], hp[ci], acc);
    }
    int pg = pxb + px;
    if (o < 36) {
        out[OUT_LOCS + pg * 36 + o] = __fadd_rn(acc, __ldg(rb + o));
    } else {
        int oc = o - 36;
        float v = __fadd_rn(acc, __ldg(cbp + oc));
        out[OUT_CLS1 + pg * 18 + oc] = v;
        out[OUT_CLS2 + pg * 18 + oc] = v;
        if (oc & 1) out[OUT_OBJ + pg * 9 + (oc >> 1)] = v;
    }
}

// ---------------- 4: anchor decode + sort keys -----------------------------
__global__ void k_decode(float* __restrict__ out) {
    int i = blockIdx.x * 256 + threadIdx.x;
    if (i < NCB)  g_rem0[i] = 0ull;
    if (i < 8000) out[OUT_ROIS + i] = 0.f;
    if (i >= NSORT) return;
    if (i >= NA) { g_key[i] = ~0ull; return; }

    int p = i / 9, a = i - p * 9;
    int ri = a / 3, si = a - ri * 3;
    double ratio = (ri == 0) ? 0.5 : (ri == 1 ? 1.0 : 2.0);
    double scale = (si == 0) ? 4.0 : (si == 1 ? 8.0 : 16.0);
    double hd = 4.0 * scale * sqrt(ratio);
    double wd = 4.0 * scale * sqrt(1.0 / ratio);
    double cyd = (double)(4 * (p / 52) + 2);
    double cxd = (double)(4 * (p % 52) + 2);
    float a0 = (float)(cyd - hd * 0.5);
    float a1 = (float)(cxd - wd * 0.5);
    float a2 = (float)(cyd + hd * 0.5);
    float a3 = (float)(cxd + wd * 0.5);

    float ah = __fsub_rn(a2, a0), aw = __fsub_rn(a3, a1);
    float acy = __fadd_rn(a0, __fmul_rn(0.5f, ah));
    float acx = __fadd_rn(a1, __fmul_rn(0.5f, aw));

    float l0 = out[OUT_LOCS + i * 4 + 0];
    float l1 = out[OUT_LOCS + i * 4 + 1];
    float l2 = out[OUT_LOCS + i * 4 + 2];
    float l3 = out[OUT_LOCS + i * 4 + 3];
    float s  = out[OUT_OBJ + i];

    float cy = __fadd_rn(__fmul_rn(l0, ah), acy);
    float cx = __fadd_rn(__fmul_rn(l1, aw), acx);
    float hh = __fmul_rn(cephes_expf(l2), ah);
    float ww = __fmul_rn(cephes_expf(l3), aw);
    float r0 = __fsub_rn(cy, __fmul_rn(0.5f, hh));
    float r1 = __fsub_rn(cx, __fmul_rn(0.5f, ww));
    float r2 = __fadd_rn(cy, __fmul_rn(0.5f, hh));
    float r3 = __fadd_rn(cx, __fmul_rn(0.5f, ww));
    r0 = fminf(fmaxf(r0, 0.f), 210.f);
    r1 = fminf(fmaxf(r1, 0.f), 210.f);
    r2 = fminf(fmaxf(r2, 0.f), 210.f);
    r3 = fminf(fmaxf(r3, 0.f), 210.f);
    float hs = __fsub_rn(r2, r0), ws = __fsub_rn(r3, r1);
    bool valid = (hs >= 16.f) && (ws >= 16.f);

    g_roi4[i] = make_float4(r0, r1, r2, r3);
    g_valid[i] = valid ? 1 : 0;

    float sm = valid ? s : __int_as_float(0xff800000);
    unsigned u = __float_as_uint(sm);
    u = (u & 0x80000000u) ? ~u : (u | 0x80000000u);
    g_key[i] = ((unsigned long long)(~u) << 32) | (unsigned long long)(unsigned)i;
}

// ---------------- 5: bitonic sort (32768 keys ascending) -------------------
__device__ __forceinline__ void cswap(unsigned long long& a, unsigned long long& b, bool asc) {
    bool sw = asc ? (a > b) : (a < b);
    if (sw) { unsigned long long tt = a; a = b; b = tt; }
}

__device__ void bitonic_tile(unsigned long long* sk, int base, int t, int s, int jmax) {
    for (int j = jmax; j >= 1; j >>= 1) {
        __syncthreads();
#pragma unroll
        for (int q = 0; q < 2; q++) {
            int p = t + q * 1024;
            int i = 2 * p - (p & (j - 1));
            bool asc = (((base + i) & s) == 0);
            unsigned long long a = sk[i], b = sk[i + j];
            cswap(a, b, asc);
            sk[i] = a; sk[i + j] = b;
        }
    }
}

__global__ __launch_bounds__(1024) void k_sort_local_full() {
    __shared__ unsigned long long sk[4096];
    int t = threadIdx.x, base = blockIdx.x * 4096;
#pragma unroll
    for (int q = 0; q < 4; q++) sk[t + q * 1024] = g_key[base + t + q * 1024];
    for (int s = 2; s <= 4096; s <<= 1) bitonic_tile(sk, base, t, s, s >> 1);
    __syncthreads();
#pragma unroll
    for (int q = 0; q < 4; q++) g_key[base + t + q * 1024] = sk[t + q * 1024];
}

__global__ __launch_bounds__(1024) void k_sort_local_tail(int s) {
    __shared__ unsigned long long sk[4096];
    int t = threadIdx.x, base = blockIdx.x * 4096;
#pragma unroll
    for (int q = 0; q < 4; q++) sk[t + q * 1024] = g_key[base + t + q * 1024];
    bitonic_tile(sk, base, t, s, 2048);
    __syncthreads();
#pragma unroll
    for (int q = 0; q < 4; q++) g_key[base + t + q * 1024] = sk[t + q * 1024];
}

__global__ void k_sort_global(int j, int s) {
    int p = blockIdx.x * 256 + threadIdx.x;
    int i = 2 * p - (p & (j - 1));
    bool asc = ((i & s) == 0);
    unsigned long long a = g_key[i], b = g_key[i + j];
    cswap(a, b, asc);
    g_key[i] = a; g_key[i + j] = b;
}

// ---------------- 6: gather sorted boxes -----------------------------------
__global__ void k_gather() {
    int i = blockIdx.x * 256 + threadIdx.x;
    if (i >= PRE) return;
    unsigned idx = (unsigned)(g_key[i] & 0xFFFFFFFFull);
    float4 b = g_roi4[idx];
    g_sbox[i] = b;
    g_sarea[i] = __fmul_rn(__fadd_rn(__fsub_rn(b.w, b.y), 1.f),
                           __fadd_rn(__fsub_rn(b.z, b.x), 1.f));
    if (!g_valid[idx]) atomicOr(&g_rem0[i >> 6], 1ull << (i & 63));
}

// ---------------- 7: IoU suppression-mask matrix (upper triangle) ----------
// grid (cc=188, rq=47), 256 threads = 4 row-chunks x 64
__global__ __launch_bounds__(256) void k_mask() {
    int cc = blockIdx.x;
    int rc = blockIdx.y * 4 + (threadIdx.x >> 6);
    int t  = threadIdx.x & 63;
    __shared__ float4 cb[64];
    __shared__ float  ca[64];
    if (threadIdx.x < 64) {
        int jg = cc * 64 + threadIdx.x;
        if (jg < PRE) { cb[threadIdx.x] = g_sbox[jg]; ca[threadIdx.x] = g_sarea[jg]; }
        else          { cb[threadIdx.x] = make_float4(0.f, 0.f, 0.f, 0.f); ca[threadIdx.x] = 0.f; }
    }
    __syncthreads();
    if (cc < rc) return;
    int ig = rc * 64 + t;
    if (ig >= PRE) return;
    float4 b = g_sbox[ig];
    float ai = g_sarea[ig];
    unsigned long long bits = 0ull;
    int jmax = min(64, PRE - cc * 64);
    for (int j = 0; j < jmax; j++) {
        int jj = cc * 64 + j;
        if (jj <= ig) continue;
        float4 c = cb[j];
        float yy1 = fmaxf(b.x, c.x), xx1 = fmaxf(b.y, c.y);
        float yy2 = fminf(b.z, c.z), xx2 = fminf(b.w, c.w);
        float dx = __fadd_rn(__fsub_rn(xx2, xx1), 1.f);
        float dy = __fadd_rn(__fsub_rn(yy2, yy1), 1.f);
        float inter = __fmul_rn(fmaxf(0.f, dx), fmaxf(0.f, dy));
        float denom = __fsub_rn(__fadd_rn(ai, ca[j]), inter);
        // fast exact-equivalent threshold test: IEEE div only in the ambiguous band
        float diff = __fsub_rn(inter, __fmul_rn(0.7f, denom));
        bool gt;
        if (fabsf(diff) > 1e-5f * denom)
            gt = (diff > 0.f);
        else
            gt = (__fdiv_rn(inter, denom) > 0.7f);
        if (gt) bits |= (1ull << j);
    }
    g_mask[(size_t)ig * NCB + cc] = bits;
}

// ---------------- 8: chunked greedy NMS + ROI write ------------------------
__global__ __launch_bounds__(256) void k_nms(float* __restrict__ out) {
    __shared__ unsigned long long remv[NCB];
    __shared__ unsigned long long sdiag[64];
    __shared__ unsigned long long s_kept;
    __shared__ int s_base, s_stop;
    int t = threadIdx.x;
    if (t < NCB) remv[t] = g_rem0[t];
    if (t == 0) { s_base = 0; s_stop = 0; }
    __syncthreads();
    for (int c = 0; c < NCB; c++) {
        if (t < 64) {
            int row = c * 64 + t;
            sdiag[t] = (row < PRE) ? g_mask[(size_t)row * NCB + c] : 0ull;
        }
        __syncthreads();
        if (t == 0) {
            unsigned long long sup = remv[c];
            if (c == NCB - 1) sup |= ~((1ull << 32) - 1ull);
            unsigned long long kept = 0ull;
            unsigned long long avail = ~sup;
            while (avail) {
                int i = __ffsll((long long)avail) - 1;
                kept |= (1ull << i);
                sup |= sdiag[i];
                unsigned long long lowmask = (i == 63) ? ~0ull : ((2ull << i) - 1ull);
                avail = avail & ~sup & ~lowmask;
            }
            s_kept = kept;
        }
        __syncthreads();
        unsigned long long kept = s_kept;
        int base = s_base;
        if (t < 64 && ((kept >> t) & 1ull)) {
            int pos = base + __popcll(kept & ((1ull << t) - 1ull));
            if (pos < POST) {
                float4 b = g_sbox[c * 64 + t];
                out[OUT_ROIS + pos * 4 + 0] = b.x;
                out[OUT_ROIS + pos * 4 + 1] = b.y;
                out[OUT_ROIS + pos * 4 + 2] = b.z;
                out[OUT_ROIS + pos * 4 + 3] = b.w;
            }
        }
        unsigned long long acc = 0ull;
        if (t > c && t < NCB) {
            acc = remv[t];
            unsigned long long k2 = kept;
            while (k2) {
                int i = __ffsll((long long)k2) - 1;
                k2 &= (k2 - 1ull);
                acc |= g_mask[(size_t)(c * 64 + i) * NCB + t];
            }
        }
        __syncthreads();
        if (t > c && t < NCB) remv[t] = acc;
        if (t == 0) {
            s_base = base + __popcll(kept);
            s_stop = (s_base >= POST) ? 1 : 0;
        }
        __syncthreads();
        if (s_stop) return;
    }
}

// ---------------- launch ----------------------------------------------------
extern "C" void kernel_launch(void* const* d_in, const int* in_sizes, int n_in,
                              void* d_out, int out_size) {
    const float* x   = (const float*)d_in[0];
    const float* c1w = (const float*)d_in[1];
    const float* c1b = (const float*)d_in[2];
    const float* rw  = (const float*)d_in[3];
    const float* rb  = (const float*)d_in[4];
    const float* cw  = (const float*)d_in[5];
    const float* cb  = (const float*)d_in[6];
    float* out = (float*)d_out;

    cudaFuncSetAttribute(k_conv, cudaFuncAttributeMaxDynamicSharedMemorySize, SMEM_CONV);

    k_wt<<<2304, 256>>>(c1w);
    k_conv<<<dim3(4, 52), 208, SMEM_CONV>>>(x, c1b);
    k_heads<<<676, 216>>>(rw, rb, cw, cb, out);
    k_decode<<<128, 256>>>(out);

    k_sort_local_full<<<8, 1024>>>();
    k_sort_global<<<64, 256>>>(4096, 8192);
    k_sort_local_tail<<<8, 1024>>>(8192);
    k_sort_global<<<64, 256>>>(8192, 16384);
    k_sort_global<<<64, 256>>>(4096, 16384);
    k_sort_local_tail<<<8, 1024>>>(16384);
    k_sort_global<<<64, 256>>>(16384, 32768);
    k_sort_global<<<64, 256>>>(8192, 32768);
    k_sort_global<<<64, 256>>>(4096, 32768);
    k_sort_local_tail<<<8, 1024>>>(32768);

    k_gather<<<47, 256>>>();
    k_mask<<<dim3(NCB, 47), 256>>>();
    k_nms<<<1, 256>>>(out);
}